// round 2
// baseline (speedup 1.0000x reference)
#include <cuda_runtime.h>
#include <cuda_bf16.h>
#include <cstdint>

// MeanAggregator: out[b, :] = (1/25) * sum_s features[neigh_idx[b, s], :]
//   features: [500000, 128] float32
//   neigh_idx: [65536, 25]  int64 OR int32 (detected at runtime)
//   out:       [65536, 128] float32
//
// Strategy: warp-per-row gather. Each lane owns one float4 (128 floats = 32
// lanes x float4). 25 gathers fully unrolled for MLP; each gather is a
// coalesced 512B row read across the warp. Memory-bound: ~850 MB L2-side
// traffic, ~250-450 MB DRAM (features table is 244 MB with ~3.3x reuse).

#define BATCH_N   65536
#define NSAMP     25
#define DFEAT     128
#define VEC_PER_ROW (DFEAT / 4)   // 32 float4 per row

__device__ int g_idx_is_i64;

// Detect whether the index buffer is int64 or int32.
// Values are in [0, 500000), so if stored as little-endian int64 the odd
// 32-bit words of the first 32 entries are all zero. If stored as int32,
// those odd words are random indices (all-zero probability ~1e-180).
__global__ void detect_idx_dtype_kernel(const unsigned int* __restrict__ idx_words) {
    if (threadIdx.x == 0 && blockIdx.x == 0) {
        int i64 = 1;
        #pragma unroll
        for (int i = 0; i < 32; i++) {
            if (idx_words[2 * i + 1] != 0u) { i64 = 0; break; }
        }
        g_idx_is_i64 = i64;
    }
}

__global__ __launch_bounds__(256)
void mean_agg_kernel(const float4* __restrict__ feat,
                     const void*   __restrict__ idx,
                     float4*       __restrict__ out) {
    const int gwarp = (blockIdx.x * 256 + threadIdx.x) >> 5;   // output row
    const int lane  = threadIdx.x & 31;                        // float4 slot
    if (gwarp >= BATCH_N) return;

    const long long ibase = (long long)gwarp * NSAMP;

    // Load the 25 neighbor indices (same addresses across the warp ->
    // broadcast in L1; tiny cost vs the 512B row gathers).
    int nidx[NSAMP];
    if (g_idx_is_i64) {
        const long long* __restrict__ p = (const long long*)idx + ibase;
        #pragma unroll
        for (int s = 0; s < NSAMP; s++) nidx[s] = (int)__ldg(p + s);
    } else {
        const int* __restrict__ p = (const int*)idx + ibase;
        #pragma unroll
        for (int s = 0; s < NSAMP; s++) nidx[s] = __ldg(p + s);
    }

    float4 acc = make_float4(0.f, 0.f, 0.f, 0.f);
    #pragma unroll
    for (int s = 0; s < NSAMP; s++) {
        const float4 v = __ldg(feat + (long long)nidx[s] * VEC_PER_ROW + lane);
        acc.x += v.x; acc.y += v.y; acc.z += v.z; acc.w += v.w;
    }

    const float inv = 1.0f / (float)NSAMP;
    acc.x *= inv; acc.y *= inv; acc.z *= inv; acc.w *= inv;
    out[(long long)gwarp * VEC_PER_ROW + lane] = acc;
}

extern "C" void kernel_launch(void* const* d_in, const int* in_sizes, int n_in,
                              void* d_out, int out_size) {
    const float4* feat = (const float4*)d_in[0];
    const void*   idx  = d_in[1];
    float4*       out  = (float4*)d_out;

    // 1 thread: sniff index dtype into __device__ flag (graph-capturable,
    // deterministic, stream-ordered before the main kernel).
    detect_idx_dtype_kernel<<<1, 32>>>((const unsigned int*)idx);

    // 8 warps/block -> 8 rows/block; 65536/8 = 8192 blocks.
    const int threads = 256;
    const int rows_per_block = threads / 32;
    const int blocks = (BATCH_N + rows_per_block - 1) / rows_per_block;
    mean_agg_kernel<<<blocks, threads>>>(feat, idx, out);
}

// round 4
// speedup vs baseline: 1.1097x; 1.1097x over previous
#include <cuda_runtime.h>
#include <cuda_bf16.h>
#include <cstdint>

// MeanAggregator: out[b, :] = (1/25) * sum_s features[neigh_idx[b, s], :]
//   features: [500000, 128] f32   neigh_idx: [65536, 25] i64-or-i32   out: [65536,128] f32
//
// Column-tiled 4-pass gather: pass p touches only the p-th 128B line of each
// feature row (footprint 61 MB -> L2-resident by capacity), so the ~3.3x index
// multiplicity becomes L2 hits. Each feature line crosses DRAM exactly once
// (~244 MB total vs ~580 MB for the untiled gather).

#define BATCH_N 65536
#define NSAMP   25
#define NPASS   4            // 128 floats / 32 per pass; 128B slice = one L2 line

__device__ int g_idx_is_i64;

// Index dtype sniff: values < 500000, so i64 storage => odd 32-bit words of the
// first 32 entries are all zero (i32 storage: P(all zero) ~ 1e-180).
__global__ void detect_idx_dtype_kernel(const unsigned int* __restrict__ idx_words) {
    if (threadIdx.x == 0 && blockIdx.x == 0) {
        int i64 = 1;
        #pragma unroll
        for (int i = 0; i < 32; i++)
            if (idx_words[2 * i + 1] != 0u) { i64 = 0; break; }
        g_idx_is_i64 = i64;
    }
}

__global__ __launch_bounds__(256)
void mean_agg_pass_kernel(const float4* __restrict__ feat,
                          const void*   __restrict__ idx,
                          float4*       __restrict__ out,
                          int pass) {
    const int row  = (blockIdx.x * 256 + threadIdx.x) >> 5;  // output row
    const int lane = threadIdx.x & 31;
    if (row >= BATCH_N) return;

    const int g  = lane >> 3;   // sample group 0..3 (4 samples gathered per LDG)
    const int c8 = lane & 7;    // float4 slot within the 128B slice

    // This lane's sample ids: s = 4c + g for c in 0..5, plus s = 24 (group 0).
    int nid[7];
    const long long ib = (long long)row * NSAMP;
    if (g_idx_is_i64) {
        const long long* __restrict__ p = (const long long*)idx + ib;
        #pragma unroll
        for (int c = 0; c < 6; c++) nid[c] = (int)__ldg(p + 4 * c + g);
        nid[6] = (int)__ldg(p + 24);
    } else {
        const int* __restrict__ p = (const int*)idx + ib;
        #pragma unroll
        for (int c = 0; c < 6; c++) nid[c] = __ldg(p + 4 * c + g);
        nid[6] = __ldg(p + 24);
    }

    const long long sliceoff = (long long)pass * 8 + c8;  // float4 units

    // Batch the 6 grouped gathers (each LDG.128 covers 4 samples' 128B slices),
    // then accumulate, so all loads are in flight together.
    float4 v[6];
    #pragma unroll
    for (int c = 0; c < 6; c++)
        v[c] = __ldg(feat + (long long)nid[c] * 32 + sliceoff);

    float4 acc = make_float4(0.f, 0.f, 0.f, 0.f);
    #pragma unroll
    for (int c = 0; c < 6; c++) {
        acc.x += v[c].x; acc.y += v[c].y; acc.z += v[c].z; acc.w += v[c].w;
    }
    if (g == 0) {  // sample 24, predicated quarter-warp
        float4 t = __ldg(feat + (long long)nid[6] * 32 + sliceoff);
        acc.x += t.x; acc.y += t.y; acc.z += t.z; acc.w += t.w;
    }

    // Cross-group reduction: lanes {L, L^8, L^16, L^24} hold disjoint sample
    // subsets of the same output elements.
    #pragma unroll
    for (int m = 8; m <= 16; m <<= 1) {
        acc.x += __shfl_xor_sync(0xffffffffu, acc.x, m);
        acc.y += __shfl_xor_sync(0xffffffffu, acc.y, m);
        acc.z += __shfl_xor_sync(0xffffffffu, acc.z, m);
        acc.w += __shfl_xor_sync(0xffffffffu, acc.w, m);
    }

    if (lane < 8) {
        const float inv = 1.0f / (float)NSAMP;
        acc.x *= inv; acc.y *= inv; acc.z *= inv; acc.w *= inv;
        // Streaming store (st.global.cs): out is written once, keep it from
        // displacing the L2-resident feature slice.
        __stcs(out + (long long)row * 32 + (long long)pass * 8 + lane, acc);
    }
}

extern "C" void kernel_launch(void* const* d_in, const int* in_sizes, int n_in,
                              void* d_out, int out_size) {
    const float4* feat = (const float4*)d_in[0];
    const void*   idx  = d_in[1];
    float4*       out  = (float4*)d_out;

    detect_idx_dtype_kernel<<<1, 32>>>((const unsigned int*)idx);

    const int threads = 256;
    const int blocks  = BATCH_N / (threads / 32);  // 8192
    // Sequential passes (same stream) give each 61 MB feature slice the whole
    // pass to be L2-resident before moving to the next slice.
    for (int p = 0; p < NPASS; p++)
        mean_agg_pass_kernel<<<blocks, threads>>>(feat, idx, out, p);
}